// round 1
// baseline (speedup 1.0000x reference)
#include <cuda_runtime.h>

// Problem constants
#define BB   4
#define SS   4096
#define DIN  768
#define HD   64
#define MM   (BB*SS)   // 16384 rows

// Scratch for Q, K, V projections (device globals: allocation-free)
__device__ float g_q[MM * HD];
__device__ float g_k[MM * HD];
__device__ float g_v[MM * HD];

// ---------------------------------------------------------------------------
// Kernel 1: fused QKV projection.  out = x @ W   (M=16384, K=768, N=64)
// grid = (M/128, 3), block = 256.  Tile 128x64, BK=16, micro 8x4.
// ---------------------------------------------------------------------------
__global__ __launch_bounds__(256) void qkv_kernel(
    const float* __restrict__ x,
    const float* __restrict__ Wq,
    const float* __restrict__ Wk,
    const float* __restrict__ Wv)
{
    const int which = blockIdx.y;
    const float* __restrict__ W = (which == 0) ? Wq : (which == 1) ? Wk : Wv;
    float* __restrict__ out = (which == 0) ? g_q : (which == 1) ? g_k : g_v;

    const int m0 = blockIdx.x * 128;

    __shared__ float Xs[16][132];   // [k][m], padded
    __shared__ float Ws[16][68];    // [k][n], padded (mult of 4 for float4)

    const int tid = threadIdx.x;
    const int tx = tid & 15;        // n dimension (16 * 4 = 64)
    const int ty = tid >> 4;        // m dimension (16 * 8 = 128)

    float acc[8][4];
    #pragma unroll
    for (int i = 0; i < 8; i++)
        #pragma unroll
        for (int j = 0; j < 4; j++) acc[i][j] = 0.f;

    for (int k0 = 0; k0 < DIN; k0 += 16) {
        // load x tile 128x16 (transposed into Xs[k][m])
        #pragma unroll
        for (int r = 0; r < 2; r++) {
            int f4  = tid + r * 256;        // 0..511
            int row = f4 >> 2;              // 0..127
            int kc  = (f4 & 3) * 4;         // 0,4,8,12
            float4 v = *(const float4*)&x[(size_t)(m0 + row) * DIN + k0 + kc];
            Xs[kc + 0][row] = v.x;
            Xs[kc + 1][row] = v.y;
            Xs[kc + 2][row] = v.z;
            Xs[kc + 3][row] = v.w;
        }
        // load W tile 16x64 (natural layout)
        {
            int row = tid >> 4;             // 0..15
            int col = (tid & 15) * 4;       // 0..60
            *(float4*)&Ws[row][col] = *(const float4*)&W[(size_t)(k0 + row) * HD + col];
        }
        __syncthreads();

        #pragma unroll
        for (int kk = 0; kk < 16; kk++) {
            float4 a0 = *(const float4*)&Xs[kk][ty * 8];
            float4 a1 = *(const float4*)&Xs[kk][ty * 8 + 4];
            float4 b  = *(const float4*)&Ws[kk][tx * 4];
            float a[8] = {a0.x, a0.y, a0.z, a0.w, a1.x, a1.y, a1.z, a1.w};
            float bb4[4] = {b.x, b.y, b.z, b.w};
            #pragma unroll
            for (int i = 0; i < 8; i++)
                #pragma unroll
                for (int j = 0; j < 4; j++)
                    acc[i][j] += a[i] * bb4[j];
        }
        __syncthreads();
    }

    #pragma unroll
    for (int i = 0; i < 8; i++) {
        float4 v = make_float4(acc[i][0], acc[i][1], acc[i][2], acc[i][3]);
        *(float4*)&out[(size_t)(m0 + ty * 8 + i) * HD + tx * 4] = v;
    }
}

// ---------------------------------------------------------------------------
// Kernel 2: causal flash attention, fp32.
// BM = BN = 64, 256 threads, micro 4x4.
// Load-balance: CTA pair p handles q-tiles {p, 63-p} -> 65 key-blocks each.
// grid = (32, B), one wave of 128 CTAs.
// Dynamic smem layout:
//   Qs[64][68]  (d-major, transposed)
//   Ks[64][68]  (d-major, transposed)
//   Vs[64][68]  (n-major, natural)
//   Ss[64][65]  (scores/probs, [m][n])
//   m_s[64], l_s[64], c_s[64]
// ---------------------------------------------------------------------------
#define PAD 68
#define SP  65
#define SMEM_ATTN ((3 * HD * PAD + 64 * SP + 3 * 64) * (int)sizeof(float))

__global__ __launch_bounds__(256) void attn_kernel(float* __restrict__ out)
{
    extern __shared__ float sm[];
    float (*Qs)[PAD] = (float (*)[PAD])(sm);
    float (*Ks)[PAD] = (float (*)[PAD])(sm + HD * PAD);
    float (*Vs)[PAD] = (float (*)[PAD])(sm + 2 * HD * PAD);
    float (*Ss)[SP]  = (float (*)[SP]) (sm + 3 * HD * PAD);
    float* m_s = sm + 3 * HD * PAD + 64 * SP;
    float* l_s = m_s + 64;
    float* c_s = l_s + 64;

    const int b   = blockIdx.y;
    const int p   = blockIdx.x;          // 0..31
    const int tid = threadIdx.x;
    const int tx  = tid & 15;            // n / c dimension
    const int ty  = tid >> 4;            // m dimension

    const float* __restrict__ qbase = g_q + (size_t)b * SS * HD;
    const float* __restrict__ kbase = g_k + (size_t)b * SS * HD;
    const float* __restrict__ vbase = g_v + (size_t)b * SS * HD;

    #pragma unroll 1
    for (int half = 0; half < 2; half++) {
        const int qi = (half == 0) ? p : (63 - p);

        // ---- load Q tile (transposed into Qs[d][m]), init stats ----
        #pragma unroll
        for (int r = 0; r < 4; r++) {
            int f4  = tid + r * 256;         // 0..1023
            int row = f4 >> 4;               // 0..63
            int dc  = (f4 & 15) * 4;         // 0..60
            float4 v = *(const float4*)&qbase[(size_t)(qi * 64 + row) * HD + dc];
            Qs[dc + 0][row] = v.x;
            Qs[dc + 1][row] = v.y;
            Qs[dc + 2][row] = v.z;
            Qs[dc + 3][row] = v.w;
        }
        if (tid < 64) { m_s[tid] = -1e30f; l_s[tid] = 0.f; }

        float o[4][4];
        #pragma unroll
        for (int i = 0; i < 4; i++)
            #pragma unroll
            for (int j = 0; j < 4; j++) o[i][j] = 0.f;

        __syncthreads();

        for (int kb = 0; kb <= qi; kb++) {
            // ---- load K (transposed) and V (natural) tiles ----
            #pragma unroll
            for (int r = 0; r < 4; r++) {
                int f4  = tid + r * 256;
                int row = f4 >> 4;
                int dc  = (f4 & 15) * 4;
                float4 kv = *(const float4*)&kbase[(size_t)(kb * 64 + row) * HD + dc];
                Ks[dc + 0][row] = kv.x;
                Ks[dc + 1][row] = kv.y;
                Ks[dc + 2][row] = kv.z;
                Ks[dc + 3][row] = kv.w;
                float4 vv = *(const float4*)&vbase[(size_t)(kb * 64 + row) * HD + dc];
                *(float4*)&Vs[row][dc] = vv;
            }
            __syncthreads();

            // ---- S = (Q K^T) * scale, causal mask on diag block ----
            float s[4][4];
            #pragma unroll
            for (int i = 0; i < 4; i++)
                #pragma unroll
                for (int j = 0; j < 4; j++) s[i][j] = 0.f;

            #pragma unroll 16
            for (int d = 0; d < HD; d++) {
                float4 a  = *(const float4*)&Qs[d][ty * 4];
                float4 bk = *(const float4*)&Ks[d][tx * 4];
                float av[4] = {a.x, a.y, a.z, a.w};
                float bv[4] = {bk.x, bk.y, bk.z, bk.w};
                #pragma unroll
                for (int i = 0; i < 4; i++)
                    #pragma unroll
                    for (int j = 0; j < 4; j++)
                        s[i][j] += av[i] * bv[j];
            }

            const bool diag = (kb == qi);
            #pragma unroll
            for (int i = 0; i < 4; i++) {
                #pragma unroll
                for (int j = 0; j < 4; j++) {
                    float sv = s[i][j] * 0.125f;
                    if (diag && (tx * 4 + j) > (ty * 4 + i)) sv = -1e30f;
                    Ss[ty * 4 + i][tx * 4 + j] = sv;
                }
            }
            __syncthreads();

            // ---- online softmax (64 threads, one row each) ----
            if (tid < 64) {
                float mo = m_s[tid];
                float mx = mo;
                #pragma unroll 8
                for (int n = 0; n < 64; n++) mx = fmaxf(mx, Ss[tid][n]);
                float corr = __expf(mo - mx);
                float l = l_s[tid] * corr;
                #pragma unroll 8
                for (int n = 0; n < 64; n++) {
                    float pp = __expf(Ss[tid][n] - mx);
                    Ss[tid][n] = pp;
                    l += pp;
                }
                m_s[tid] = mx;
                l_s[tid] = l;
                c_s[tid] = corr;
            }
            __syncthreads();

            // ---- rescale accumulator, then O += P @ V ----
            float cr[4];
            #pragma unroll
            for (int i = 0; i < 4; i++) cr[i] = c_s[ty * 4 + i];
            #pragma unroll
            for (int i = 0; i < 4; i++)
                #pragma unroll
                for (int j = 0; j < 4; j++) o[i][j] *= cr[i];

            #pragma unroll 8
            for (int n = 0; n < 64; n++) {
                float4 vv = *(const float4*)&Vs[n][tx * 4];
                #pragma unroll
                for (int i = 0; i < 4; i++) {
                    float pp = Ss[ty * 4 + i][n];
                    o[i][0] += pp * vv.x;
                    o[i][1] += pp * vv.y;
                    o[i][2] += pp * vv.z;
                    o[i][3] += pp * vv.w;
                }
            }
            __syncthreads();   // protect Ks/Vs/Ss before next iteration
        }

        // ---- normalize and write out ----
        #pragma unroll
        for (int i = 0; i < 4; i++) {
            int m = ty * 4 + i;
            float linv = 1.0f / l_s[m];
            float4 r = make_float4(o[i][0] * linv, o[i][1] * linv,
                                   o[i][2] * linv, o[i][3] * linv);
            *(float4*)&out[(size_t)(b * SS + qi * 64 + m) * HD + tx * 4] = r;
        }
        __syncthreads();       // protect Qs / stats before next half
    }
}

// ---------------------------------------------------------------------------
// kernel_launch
// ---------------------------------------------------------------------------
extern "C" void kernel_launch(void* const* d_in, const int* in_sizes, int n_in,
                              void* d_out, int out_size)
{
    const float* x  = (const float*)d_in[0];
    const float* Wq = (const float*)d_in[1];
    const float* Wk = (const float*)d_in[2];
    const float* Wv = (const float*)d_in[3];
    float* out = (float*)d_out;

    // Opt-in to >48KB dynamic smem for the attention kernel (idempotent).
    static int smem_set = 0;
    if (!smem_set) {
        cudaFuncSetAttribute(attn_kernel,
                             cudaFuncAttributeMaxDynamicSharedMemorySize,
                             SMEM_ATTN);
        smem_set = 1;
    }

    dim3 g1(MM / 128, 3);
    qkv_kernel<<<g1, 256>>>(x, Wq, Wk, Wv);

    dim3 g2(32, BB);
    attn_kernel<<<g2, 256, SMEM_ATTN>>>(out);
}